// round 1
// baseline (speedup 1.0000x reference)
#include <cuda_runtime.h>
#include <cuda_bf16.h>

#define N_USERS 40000
#define N_ITEMS 20000
#define NNZ     1000000
#define D       64
#define N_TOTAL (N_USERS + N_ITEMS)
#define EPS     1e-8f

// ---------------- device scratch (no dynamic allocation allowed) ----------------
__device__ float g_cur_u[N_USERS * D];
__device__ float g_nxt_u[N_USERS * D];
__device__ float g_cur_i[N_ITEMS * D];
__device__ float g_nxt_i[N_ITEMS * D];
__device__ float g_inv_u[N_USERS];
__device__ float g_inv_i[N_ITEMS];
__device__ float g_w_edge[NNZ];   // (sim+1)/2 in u-sorted edge order
__device__ float g_w_u[NNZ];      // row-normalized, u-order
__device__ float g_w_i[NNZ];      // row-normalized, i-order
__device__ int   g_i_src_u[NNZ];  // source user per i-ordered slot
__device__ int   g_i_edge[NNZ];   // i-ordered slot -> original edge id
__device__ int   g_u_ptr[N_USERS + 1];
__device__ int   g_i_ptr[N_ITEMS + 1];
__device__ int   g_i_cnt[N_ITEMS];

// ---------------- CSR construction ----------------
__global__ void k_uptr(const int* __restrict__ u_idx) {
    int u = blockIdx.x * blockDim.x + threadIdx.x;
    if (u > N_USERS) return;
    int lo = 0, hi = NNZ;
    while (lo < hi) { int mid = (lo + hi) >> 1; if (u_idx[mid] < u) lo = mid + 1; else hi = mid; }
    g_u_ptr[u] = lo;
}

__global__ void k_zero_cnt() {
    int i = blockIdx.x * blockDim.x + threadIdx.x;
    if (i < N_ITEMS) g_i_cnt[i] = 0;
}

__global__ void k_count(const int* __restrict__ i_idx) {
    int e = blockIdx.x * blockDim.x + threadIdx.x;
    if (e < NNZ) atomicAdd(&g_i_cnt[i_idx[e]], 1);
}

// single-block exclusive scan of g_i_cnt -> g_i_ptr, re-zeroing g_i_cnt as cursor
__global__ void k_scan() {
    const int T = 1024;
    __shared__ int warp_sums[32];
    __shared__ int carry_s;
    int tid = threadIdx.x, lane = tid & 31, wid = tid >> 5;
    if (tid == 0) { carry_s = 0; g_i_ptr[0] = 0; }
    __syncthreads();
    for (int base = 0; base < N_ITEMS; base += T) {
        int idx = base + tid;
        int v = (idx < N_ITEMS) ? g_i_cnt[idx] : 0;
        if (idx < N_ITEMS) g_i_cnt[idx] = 0;
        int x = v;
        #pragma unroll
        for (int o = 1; o < 32; o <<= 1) { int y = __shfl_up_sync(0xffffffffu, x, o); if (lane >= o) x += y; }
        if (lane == 31) warp_sums[wid] = x;
        __syncthreads();
        if (wid == 0) {
            int s = warp_sums[lane];
            #pragma unroll
            for (int o = 1; o < 32; o <<= 1) { int y = __shfl_up_sync(0xffffffffu, s, o); if (lane >= o) s += y; }
            warp_sums[lane] = s;
        }
        __syncthreads();
        int carry = carry_s;
        int incl = x + (wid > 0 ? warp_sums[wid - 1] : 0) + carry;
        if (idx < N_ITEMS) g_i_ptr[idx + 1] = incl;
        __syncthreads();
        if (tid == T - 1) carry_s = incl;
        __syncthreads();
    }
}

__global__ void k_scatter(const int* __restrict__ u_idx, const int* __restrict__ i_idx) {
    int e = blockIdx.x * blockDim.x + threadIdx.x;
    if (e >= NNZ) return;
    int i = i_idx[e];
    int pos = g_i_ptr[i] + atomicAdd(&g_i_cnt[i], 1);
    g_i_src_u[pos] = u_idx[e];
    g_i_edge[pos]  = e;
}

// ---------------- embeddings (warp per row, lane owns 2 cols) ----------------
__global__ void __launch_bounds__(256) k_emb_user(const float* __restrict__ user_linear,
                                                  const int* __restrict__ i_idx,
                                                  float* __restrict__ out) {
    int w = (blockIdx.x * blockDim.x + threadIdx.x) >> 5;
    if (w >= N_USERS) return;
    int lane = threadIdx.x & 31;
    int beg = g_u_ptr[w], end = g_u_ptr[w + 1];
    float2 acc = make_float2(0.f, 0.f);
    int e = beg;
    for (; e + 4 <= end; e += 4) {
        int i0 = i_idx[e], i1 = i_idx[e + 1], i2 = i_idx[e + 2], i3 = i_idx[e + 3];
        float2 v0 = *(const float2*)(user_linear + i0 * D + 2 * lane);
        float2 v1 = *(const float2*)(user_linear + i1 * D + 2 * lane);
        float2 v2 = *(const float2*)(user_linear + i2 * D + 2 * lane);
        float2 v3 = *(const float2*)(user_linear + i3 * D + 2 * lane);
        acc.x += v0.x + v1.x + v2.x + v3.x;
        acc.y += v0.y + v1.y + v2.y + v3.y;
    }
    for (; e < end; ++e) {
        int i = i_idx[e];
        float2 v = *(const float2*)(user_linear + i * D + 2 * lane);
        acc.x += v.x; acc.y += v.y;
    }
    float ss = acc.x * acc.x + acc.y * acc.y;
    #pragma unroll
    for (int o = 16; o; o >>= 1) ss += __shfl_xor_sync(0xffffffffu, ss, o);
    if (lane == 0) g_inv_u[w] = 1.0f / fmaxf(sqrtf(ss), EPS);
    *(float2*)(g_cur_u + w * D + 2 * lane) = acc;
    *(float2*)(out + (size_t)w * D + 2 * lane) = acc;
}

__global__ void __launch_bounds__(256) k_emb_item(const float* __restrict__ item_linear,
                                                  float* __restrict__ out) {
    int w = (blockIdx.x * blockDim.x + threadIdx.x) >> 5;
    if (w >= N_ITEMS) return;
    int lane = threadIdx.x & 31;
    int beg = g_i_ptr[w], end = g_i_ptr[w + 1];
    float2 acc = make_float2(0.f, 0.f);
    int p = beg;
    for (; p + 4 <= end; p += 4) {
        int u0 = g_i_src_u[p], u1 = g_i_src_u[p + 1], u2 = g_i_src_u[p + 2], u3 = g_i_src_u[p + 3];
        float2 v0 = *(const float2*)(item_linear + u0 * D + 2 * lane);
        float2 v1 = *(const float2*)(item_linear + u1 * D + 2 * lane);
        float2 v2 = *(const float2*)(item_linear + u2 * D + 2 * lane);
        float2 v3 = *(const float2*)(item_linear + u3 * D + 2 * lane);
        acc.x += v0.x + v1.x + v2.x + v3.x;
        acc.y += v0.y + v1.y + v2.y + v3.y;
    }
    for (; p < end; ++p) {
        int u = g_i_src_u[p];
        float2 v = *(const float2*)(item_linear + u * D + 2 * lane);
        acc.x += v.x; acc.y += v.y;
    }
    float ss = acc.x * acc.x + acc.y * acc.y;
    #pragma unroll
    for (int o = 16; o; o >>= 1) ss += __shfl_xor_sync(0xffffffffu, ss, o);
    if (lane == 0) g_inv_i[w] = 1.0f / fmaxf(sqrtf(ss), EPS);
    *(float2*)(g_cur_i + w * D + 2 * lane) = acc;
    *(float2*)(out + (size_t)(N_USERS + w) * D + 2 * lane) = acc;
}

// ---------------- per-edge cosine weights (warp per edge) ----------------
__global__ void __launch_bounds__(256) k_weights(const int* __restrict__ u_idx,
                                                 const int* __restrict__ i_idx) {
    int e = (blockIdx.x * blockDim.x + threadIdx.x) >> 5;
    if (e >= NNZ) return;
    int lane = threadIdx.x & 31;
    int u = u_idx[e], i = i_idx[e];
    float2 a = *(const float2*)(g_cur_u + u * D + 2 * lane);
    float2 b = *(const float2*)(g_cur_i + i * D + 2 * lane);
    float p = a.x * b.x + a.y * b.y;
    #pragma unroll
    for (int o = 16; o; o >>= 1) p += __shfl_xor_sync(0xffffffffu, p, o);
    if (lane == 0) {
        float s = p * g_inv_u[u] * g_inv_i[i];
        g_w_edge[e] = (s + 1.0f) * 0.5f;
    }
}

// ---------------- row normalization of weights ----------------
__global__ void k_norm_u() {
    int u = blockIdx.x * blockDim.x + threadIdx.x;
    if (u >= N_USERS) return;
    int beg = g_u_ptr[u], end = g_u_ptr[u + 1];
    float s = 0.f;
    for (int e = beg; e < end; ++e) s += g_w_edge[e];
    float invd = 1.0f / (s + 1e-7f);
    for (int e = beg; e < end; ++e) g_w_u[e] = g_w_edge[e] * invd;
}

__global__ void k_norm_i() {
    int i = blockIdx.x * blockDim.x + threadIdx.x;
    if (i >= N_ITEMS) return;
    int beg = g_i_ptr[i], end = g_i_ptr[i + 1];
    float s = 0.f;
    for (int p = beg; p < end; ++p) s += g_w_edge[g_i_edge[p]];
    float invd = 1.0f / (s + 1e-7f);
    for (int p = beg; p < end; ++p) g_w_i[p] = g_w_edge[g_i_edge[p]] * invd;
}

// ---------------- propagation (warp per row, zero atomics) ----------------
__global__ void __launch_bounds__(256) k_prop_user(const int* __restrict__ i_idx,
                                                   float* __restrict__ out,
                                                   int src_is_cur, float scale) {
    int u = (blockIdx.x * blockDim.x + threadIdx.x) >> 5;
    if (u >= N_USERS) return;
    int lane = threadIdx.x & 31;
    const float* __restrict__ src = src_is_cur ? g_cur_i : g_nxt_i;
    float* __restrict__ dst = src_is_cur ? g_nxt_u : g_cur_u;
    int beg = g_u_ptr[u], end = g_u_ptr[u + 1];
    float2 acc = make_float2(0.f, 0.f);
    int e = beg;
    for (; e + 4 <= end; e += 4) {
        int i0 = i_idx[e], i1 = i_idx[e + 1], i2 = i_idx[e + 2], i3 = i_idx[e + 3];
        float w0 = g_w_u[e], w1 = g_w_u[e + 1], w2 = g_w_u[e + 2], w3 = g_w_u[e + 3];
        float2 v0 = *(const float2*)(src + i0 * D + 2 * lane);
        float2 v1 = *(const float2*)(src + i1 * D + 2 * lane);
        float2 v2 = *(const float2*)(src + i2 * D + 2 * lane);
        float2 v3 = *(const float2*)(src + i3 * D + 2 * lane);
        acc.x += w0 * v0.x + w1 * v1.x + w2 * v2.x + w3 * v3.x;
        acc.y += w0 * v0.y + w1 * v1.y + w2 * v2.y + w3 * v3.y;
    }
    for (; e < end; ++e) {
        int i = i_idx[e];
        float w = g_w_u[e];
        float2 v = *(const float2*)(src + i * D + 2 * lane);
        acc.x += w * v.x; acc.y += w * v.y;
    }
    *(float2*)(dst + u * D + 2 * lane) = acc;
    float2 o = *(float2*)(out + (size_t)u * D + 2 * lane);
    o.x = (o.x + acc.x) * scale;
    o.y = (o.y + acc.y) * scale;
    *(float2*)(out + (size_t)u * D + 2 * lane) = o;
}

__global__ void __launch_bounds__(256) k_prop_item(float* __restrict__ out,
                                                   int src_is_cur, float scale) {
    int i = (blockIdx.x * blockDim.x + threadIdx.x) >> 5;
    if (i >= N_ITEMS) return;
    int lane = threadIdx.x & 31;
    const float* __restrict__ src = src_is_cur ? g_cur_u : g_nxt_u;
    float* __restrict__ dst = src_is_cur ? g_nxt_i : g_cur_i;
    int beg = g_i_ptr[i], end = g_i_ptr[i + 1];
    float2 acc = make_float2(0.f, 0.f);
    int p = beg;
    for (; p + 4 <= end; p += 4) {
        int u0 = g_i_src_u[p], u1 = g_i_src_u[p + 1], u2 = g_i_src_u[p + 2], u3 = g_i_src_u[p + 3];
        float w0 = g_w_i[p], w1 = g_w_i[p + 1], w2 = g_w_i[p + 2], w3 = g_w_i[p + 3];
        float2 v0 = *(const float2*)(src + u0 * D + 2 * lane);
        float2 v1 = *(const float2*)(src + u1 * D + 2 * lane);
        float2 v2 = *(const float2*)(src + u2 * D + 2 * lane);
        float2 v3 = *(const float2*)(src + u3 * D + 2 * lane);
        acc.x += w0 * v0.x + w1 * v1.x + w2 * v2.x + w3 * v3.x;
        acc.y += w0 * v0.y + w1 * v1.y + w2 * v2.y + w3 * v3.y;
    }
    for (; p < end; ++p) {
        int u = g_i_src_u[p];
        float w = g_w_i[p];
        float2 v = *(const float2*)(src + u * D + 2 * lane);
        acc.x += w * v.x; acc.y += w * v.y;
    }
    *(float2*)(dst + i * D + 2 * lane) = acc;
    float2 o = *(float2*)(out + (size_t)(N_USERS + i) * D + 2 * lane);
    o.x = (o.x + acc.x) * scale;
    o.y = (o.y + acc.y) * scale;
    *(float2*)(out + (size_t)(N_USERS + i) * D + 2 * lane) = o;
}

// ---------------- launch ----------------
extern "C" void kernel_launch(void* const* d_in, const int* in_sizes, int n_in,
                              void* d_out, int out_size) {
    const float* user_linear = (const float*)d_in[0];
    const float* item_linear = (const float*)d_in[1];
    const int*   u_idx       = (const int*)d_in[2];
    const int*   i_idx       = (const int*)d_in[3];
    float* out = (float*)d_out;

    // CSR construction
    k_uptr<<<(N_USERS + 1 + 255) / 256, 256>>>(u_idx);
    k_zero_cnt<<<(N_ITEMS + 255) / 256, 256>>>();
    k_count<<<(NNZ + 255) / 256, 256>>>(i_idx);
    k_scan<<<1, 1024>>>();
    k_scatter<<<(NNZ + 255) / 256, 256>>>(u_idx, i_idx);

    // base embeddings (also initialize d_out accumulator and cur buffers)
    k_emb_user<<<(N_USERS * 32 + 255) / 256, 256>>>(user_linear, i_idx, out);
    k_emb_item<<<(N_ITEMS * 32 + 255) / 256, 256>>>(item_linear, out);

    // per-edge cosine weights + row normalization
    k_weights<<<(NNZ * 32 + 255) / 256, 256>>>(u_idx, i_idx);
    k_norm_u<<<(N_USERS + 255) / 256, 256>>>();
    k_norm_i<<<(N_ITEMS + 255) / 256, 256>>>();

    // 3 propagation layers; last one applies the /4 mean
    // layer 1: read cur, write nxt
    k_prop_user<<<(N_USERS * 32 + 255) / 256, 256>>>(i_idx, out, 1, 1.0f);
    k_prop_item<<<(N_ITEMS * 32 + 255) / 256, 256>>>(out, 1, 1.0f);
    // layer 2: read nxt, write cur
    k_prop_user<<<(N_USERS * 32 + 255) / 256, 256>>>(i_idx, out, 0, 1.0f);
    k_prop_item<<<(N_ITEMS * 32 + 255) / 256, 256>>>(out, 0, 1.0f);
    // layer 3: read cur, write nxt, final scale 0.25
    k_prop_user<<<(N_USERS * 32 + 255) / 256, 256>>>(i_idx, out, 1, 0.25f);
    k_prop_item<<<(N_ITEMS * 32 + 255) / 256, 256>>>(out, 1, 0.25f);
}

// round 2
// speedup vs baseline: 1.0428x; 1.0428x over previous
#include <cuda_runtime.h>
#include <cuda_fp16.h>
#include <cuda_bf16.h>

#define N_USERS 40000
#define N_ITEMS 20000
#define NNZ     1000000
#define D       64
#define DH      (D/2)          // 32 half2 per row
#define N_TOTAL (N_USERS + N_ITEMS)
#define EPS     1e-8f

// ---------------- device scratch (no dynamic allocation allowed) ----------------
__device__ __half2 g_lin_u_h[N_ITEMS * DH];   // user_linear fp16  [N_ITEMS, D]
__device__ __half2 g_lin_i_h[N_USERS * DH];   // item_linear fp16  [N_USERS, D]
__device__ __half2 g_emb_u0[N_USERS * DH];    // user emb ping-pong
__device__ __half2 g_emb_u1[N_USERS * DH];
__device__ __half2 g_emb_i0[N_ITEMS * DH];
__device__ __half2 g_emb_i1[N_ITEMS * DH];
__device__ float   g_inv_u[N_USERS];
__device__ float   g_inv_i[N_ITEMS];
__device__ float   g_w_u[NNZ];      // weights in u-sorted order
__device__ float   g_w_i[NNZ];      // weights in i-sorted order
__device__ int     g_i_src_u[NNZ];  // i-ordered slot -> source user
__device__ int     g_slot[NNZ];     // edge (u-order) -> i-order slot
__device__ int     g_u_ptr[N_USERS + 1];
__device__ int     g_i_ptr[N_ITEMS + 1];
__device__ int     g_i_cnt[N_ITEMS];

// ---------------- CSR construction ----------------
__global__ void k_uptr(const int* __restrict__ u_idx) {
    int u = blockIdx.x * blockDim.x + threadIdx.x;
    if (u > N_USERS) return;
    int lo = 0, hi = NNZ;
    while (lo < hi) { int mid = (lo + hi) >> 1; if (u_idx[mid] < u) lo = mid + 1; else hi = mid; }
    g_u_ptr[u] = lo;
}

__global__ void k_zero_cnt() {
    int i = blockIdx.x * blockDim.x + threadIdx.x;
    if (i < N_ITEMS) g_i_cnt[i] = 0;
}

__global__ void k_count(const int* __restrict__ i_idx) {
    int e = blockIdx.x * blockDim.x + threadIdx.x;
    if (e < NNZ) atomicAdd(&g_i_cnt[i_idx[e]], 1);
}

// single-block thread-coarsened exclusive scan: g_i_cnt -> g_i_ptr, zeroing g_i_cnt
__global__ void __launch_bounds__(1024) k_scan() {
    const int C = 20;  // 1024 * 20 >= 20000
    __shared__ int wsum[32];
    int tid = threadIdx.x, lane = tid & 31, wid = tid >> 5;
    int base = tid * C;
    int v[C];
    int s = 0;
    #pragma unroll
    for (int k = 0; k < C; ++k) {
        int idx = base + k;
        int x = (idx < N_ITEMS) ? g_i_cnt[idx] : 0;
        v[k] = s;          // thread-local exclusive prefix
        s += x;
    }
    // warp-inclusive scan of per-thread totals
    int t = s;
    #pragma unroll
    for (int o = 1; o < 32; o <<= 1) { int y = __shfl_up_sync(0xffffffffu, t, o); if (lane >= o) t += y; }
    if (lane == 31) wsum[wid] = t;
    __syncthreads();
    if (wid == 0) {
        int x = wsum[lane];
        #pragma unroll
        for (int o = 1; o < 32; o <<= 1) { int y = __shfl_up_sync(0xffffffffu, x, o); if (lane >= o) x += y; }
        wsum[lane] = x;
    }
    __syncthreads();
    int offset = (t - s) + (wid ? wsum[wid - 1] : 0);  // exclusive prefix for this thread
    #pragma unroll
    for (int k = 0; k < C; ++k) {
        int idx = base + k;
        if (idx < N_ITEMS) { g_i_ptr[idx] = offset + v[k]; g_i_cnt[idx] = 0; }
    }
    if (tid == 1023) g_i_ptr[N_ITEMS] = offset + s;
}

__global__ void k_scatter(const int* __restrict__ u_idx, const int* __restrict__ i_idx) {
    int e = blockIdx.x * blockDim.x + threadIdx.x;
    if (e >= NNZ) return;
    int i = i_idx[e];
    int pos = g_i_ptr[i] + atomicAdd(&g_i_cnt[i], 1);
    g_i_src_u[pos] = u_idx[e];
    g_slot[e] = pos;
}

// ---------------- convert linear tables to fp16 ----------------
__global__ void k_cvt(const float* __restrict__ user_linear, const float* __restrict__ item_linear) {
    int j = blockIdx.x * blockDim.x + threadIdx.x;
    const int NU = N_ITEMS * DH;        // user_linear has N_ITEMS rows
    const int NI = N_USERS * DH;
    if (j < NU) {
        float2 v = *(const float2*)(user_linear + 2 * j);
        g_lin_u_h[j] = __floats2half2_rn(v.x, v.y);
    } else if (j < NU + NI) {
        int k = j - NU;
        float2 v = *(const float2*)(item_linear + 2 * k);
        g_lin_i_h[k] = __floats2half2_rn(v.x, v.y);
    }
}

// ---------------- base embeddings (warp per row, lane owns a half2) ----------------
__global__ void __launch_bounds__(256) k_emb_user(const int* __restrict__ i_idx,
                                                  float* __restrict__ out) {
    int w = (blockIdx.x * blockDim.x + threadIdx.x) >> 5;
    if (w >= N_USERS) return;
    int lane = threadIdx.x & 31;
    int beg = g_u_ptr[w], end = g_u_ptr[w + 1];
    float2 acc = make_float2(0.f, 0.f);
    int e = beg;
    for (; e + 4 <= end; e += 4) {
        float2 v0 = __half22float2(g_lin_u_h[i_idx[e]     * DH + lane]);
        float2 v1 = __half22float2(g_lin_u_h[i_idx[e + 1] * DH + lane]);
        float2 v2 = __half22float2(g_lin_u_h[i_idx[e + 2] * DH + lane]);
        float2 v3 = __half22float2(g_lin_u_h[i_idx[e + 3] * DH + lane]);
        acc.x += v0.x + v1.x + v2.x + v3.x;
        acc.y += v0.y + v1.y + v2.y + v3.y;
    }
    for (; e < end; ++e) {
        float2 v = __half22float2(g_lin_u_h[i_idx[e] * DH + lane]);
        acc.x += v.x; acc.y += v.y;
    }
    float ss = acc.x * acc.x + acc.y * acc.y;
    #pragma unroll
    for (int o = 16; o; o >>= 1) ss += __shfl_xor_sync(0xffffffffu, ss, o);
    if (lane == 0) g_inv_u[w] = 1.0f / fmaxf(sqrtf(ss), EPS);
    g_emb_u0[w * DH + lane] = __floats2half2_rn(acc.x, acc.y);
    *(float2*)(out + (size_t)w * D + 2 * lane) = acc;
}

__global__ void __launch_bounds__(256) k_emb_item(float* __restrict__ out) {
    int w = (blockIdx.x * blockDim.x + threadIdx.x) >> 5;
    if (w >= N_ITEMS) return;
    int lane = threadIdx.x & 31;
    int beg = g_i_ptr[w], end = g_i_ptr[w + 1];
    float2 acc = make_float2(0.f, 0.f);
    int p = beg;
    for (; p + 4 <= end; p += 4) {
        float2 v0 = __half22float2(g_lin_i_h[g_i_src_u[p]     * DH + lane]);
        float2 v1 = __half22float2(g_lin_i_h[g_i_src_u[p + 1] * DH + lane]);
        float2 v2 = __half22float2(g_lin_i_h[g_i_src_u[p + 2] * DH + lane]);
        float2 v3 = __half22float2(g_lin_i_h[g_i_src_u[p + 3] * DH + lane]);
        acc.x += v0.x + v1.x + v2.x + v3.x;
        acc.y += v0.y + v1.y + v2.y + v3.y;
    }
    for (; p < end; ++p) {
        float2 v = __half22float2(g_lin_i_h[g_i_src_u[p] * DH + lane]);
        acc.x += v.x; acc.y += v.y;
    }
    float ss = acc.x * acc.x + acc.y * acc.y;
    #pragma unroll
    for (int o = 16; o; o >>= 1) ss += __shfl_xor_sync(0xffffffffu, ss, o);
    if (lane == 0) g_inv_i[w] = 1.0f / fmaxf(sqrtf(ss), EPS);
    g_emb_i0[w * DH + lane] = __floats2half2_rn(acc.x, acc.y);
    *(float2*)(out + (size_t)(N_USERS + w) * D + 2 * lane) = acc;
}

// ---------------- per-edge cosine weights (warp per edge, writes both orders) ----------------
__global__ void __launch_bounds__(256) k_weights(const int* __restrict__ u_idx,
                                                 const int* __restrict__ i_idx) {
    int e = (blockIdx.x * blockDim.x + threadIdx.x) >> 5;
    if (e >= NNZ) return;
    int lane = threadIdx.x & 31;
    int u = u_idx[e], i = i_idx[e];
    float2 a = __half22float2(g_emb_u0[u * DH + lane]);
    float2 b = __half22float2(g_emb_i0[i * DH + lane]);
    float p = a.x * b.x + a.y * b.y;
    #pragma unroll
    for (int o = 16; o; o >>= 1) p += __shfl_xor_sync(0xffffffffu, p, o);
    if (lane == 0) {
        float s = p * g_inv_u[u] * g_inv_i[i];
        float w = (s + 1.0f) * 0.5f;
        g_w_u[e] = w;
        g_w_i[g_slot[e]] = w;
    }
}

// ---------------- row normalization (both sides, in place) ----------------
__global__ void k_norm() {
    int r = blockIdx.x * blockDim.x + threadIdx.x;
    if (r >= N_TOTAL) return;
    float* w;
    int beg, end;
    if (r < N_USERS) { w = g_w_u; beg = g_u_ptr[r]; end = g_u_ptr[r + 1]; }
    else             { w = g_w_i; beg = g_i_ptr[r - N_USERS]; end = g_i_ptr[r - N_USERS + 1]; }
    float s = 0.f;
    for (int e = beg; e < end; ++e) s += w[e];
    float invd = 1.0f / (s + 1e-7f);
    for (int e = beg; e < end; ++e) w[e] *= invd;
}

// ---------------- fused propagation layer (warp per row, zero atomics) ----------------
__global__ void __launch_bounds__(256) k_prop(const int* __restrict__ i_idx,
                                              float* __restrict__ out,
                                              int flip, float scale) {
    int r = (blockIdx.x * blockDim.x + threadIdx.x) >> 5;
    if (r >= N_TOTAL) return;
    int lane = threadIdx.x & 31;
    float2 acc = make_float2(0.f, 0.f);
    if (r < N_USERS) {
        const __half2* __restrict__ src = flip ? g_emb_i1 : g_emb_i0;
        __half2* __restrict__ dst = flip ? g_emb_u0 : g_emb_u1;
        int beg = g_u_ptr[r], end = g_u_ptr[r + 1];
        int e = beg;
        for (; e + 4 <= end; e += 4) {
            float w0 = g_w_u[e], w1 = g_w_u[e + 1], w2 = g_w_u[e + 2], w3 = g_w_u[e + 3];
            float2 v0 = __half22float2(src[i_idx[e]     * DH + lane]);
            float2 v1 = __half22float2(src[i_idx[e + 1] * DH + lane]);
            float2 v2 = __half22float2(src[i_idx[e + 2] * DH + lane]);
            float2 v3 = __half22float2(src[i_idx[e + 3] * DH + lane]);
            acc.x += w0 * v0.x + w1 * v1.x + w2 * v2.x + w3 * v3.x;
            acc.y += w0 * v0.y + w1 * v1.y + w2 * v2.y + w3 * v3.y;
        }
        for (; e < end; ++e) {
            float w = g_w_u[e];
            float2 v = __half22float2(src[i_idx[e] * DH + lane]);
            acc.x += w * v.x; acc.y += w * v.y;
        }
        dst[r * DH + lane] = __floats2half2_rn(acc.x, acc.y);
    } else {
        int i = r - N_USERS;
        const __half2* __restrict__ src = flip ? g_emb_u1 : g_emb_u0;
        __half2* __restrict__ dst = flip ? g_emb_i0 : g_emb_i1;
        int beg = g_i_ptr[i], end = g_i_ptr[i + 1];
        int p = beg;
        for (; p + 4 <= end; p += 4) {
            float w0 = g_w_i[p], w1 = g_w_i[p + 1], w2 = g_w_i[p + 2], w3 = g_w_i[p + 3];
            float2 v0 = __half22float2(src[g_i_src_u[p]     * DH + lane]);
            float2 v1 = __half22float2(src[g_i_src_u[p + 1] * DH + lane]);
            float2 v2 = __half22float2(src[g_i_src_u[p + 2] * DH + lane]);
            float2 v3 = __half22float2(src[g_i_src_u[p + 3] * DH + lane]);
            acc.x += w0 * v0.x + w1 * v1.x + w2 * v2.x + w3 * v3.x;
            acc.y += w0 * v0.y + w1 * v1.y + w2 * v2.y + w3 * v3.y;
        }
        for (; p < end; ++p) {
            float w = g_w_i[p];
            float2 v = __half22float2(src[g_i_src_u[p] * DH + lane]);
            acc.x += w * v.x; acc.y += w * v.y;
        }
        dst[i * DH + lane] = __floats2half2_rn(acc.x, acc.y);
    }
    float2 o = *(float2*)(out + (size_t)r * D + 2 * lane);
    o.x = (o.x + acc.x) * scale;
    o.y = (o.y + acc.y) * scale;
    *(float2*)(out + (size_t)r * D + 2 * lane) = o;
}

// ---------------- launch ----------------
extern "C" void kernel_launch(void* const* d_in, const int* in_sizes, int n_in,
                              void* d_out, int out_size) {
    const float* user_linear = (const float*)d_in[0];
    const float* item_linear = (const float*)d_in[1];
    const int*   u_idx       = (const int*)d_in[2];
    const int*   i_idx       = (const int*)d_in[3];
    float* out = (float*)d_out;

    // CSR construction + fp16 table conversion (independent, cheap)
    k_uptr<<<(N_USERS + 1 + 255) / 256, 256>>>(u_idx);
    k_zero_cnt<<<(N_ITEMS + 255) / 256, 256>>>();
    k_count<<<(NNZ + 255) / 256, 256>>>(i_idx);
    k_scan<<<1, 1024>>>();
    k_scatter<<<(NNZ + 255) / 256, 256>>>(u_idx, i_idx);
    {
        int total = (N_ITEMS + N_USERS) * DH;
        k_cvt<<<(total + 255) / 256, 256>>>(user_linear, item_linear);
    }

    // base embeddings (also initialize d_out accumulator)
    k_emb_user<<<(N_USERS * 32 + 255) / 256, 256>>>(i_idx, out);
    k_emb_item<<<(N_ITEMS * 32 + 255) / 256, 256>>>(out);

    // per-edge cosine weights + row normalization
    k_weights<<<(NNZ * 32 + 255) / 256, 256>>>(u_idx, i_idx);
    k_norm<<<(N_TOTAL + 255) / 256, 256>>>();

    // 3 fused propagation layers; last one applies the /4 mean
    k_prop<<<(N_TOTAL * 32 + 255) / 256, 256>>>(i_idx, out, 0, 1.0f);
    k_prop<<<(N_TOTAL * 32 + 255) / 256, 256>>>(i_idx, out, 1, 1.0f);
    k_prop<<<(N_TOTAL * 32 + 255) / 256, 256>>>(i_idx, out, 0, 0.25f);
}

// round 3
// speedup vs baseline: 1.7510x; 1.6791x over previous
#include <cuda_runtime.h>
#include <cuda_fp16.h>

#define N_USERS 40000
#define N_ITEMS 20000
#define NNZ     1000000
#define D       64
#define N_TOTAL (N_USERS + N_ITEMS)
#define EPS     1e-8f
#define SCAN_BLOCKS 20
#define SCAN_CHUNK  1000

// ---------------- device scratch ----------------
// fp16 rows stored as 8 x uint4 (= 32 half2 = 64 halfs = 128B) per row
__device__ uint4 g_lin_u[N_ITEMS * 8];   // user_linear fp16
__device__ uint4 g_lin_i[N_USERS * 8];   // item_linear fp16
__device__ uint4 g_emb_u0[N_USERS * 8];
__device__ uint4 g_emb_u1[N_USERS * 8];
__device__ uint4 g_emb_i0[N_ITEMS * 8];
__device__ uint4 g_emb_i1[N_ITEMS * 8];
__device__ float g_inv_u[N_USERS];
__device__ float g_inv_i[N_ITEMS];
__device__ float g_w_u[NNZ];        // unnormalized w, u-order (temp)
__device__ float g_w_i[NNZ];        // unnormalized w, i-order (temp)
__device__ int2  g_pk_u[NNZ];       // packed {i_idx, w_norm} u-order
__device__ int2  g_pk_i[NNZ];       // packed {src_u, w_norm} i-order
__device__ int   g_i_src_u[NNZ];
__device__ int   g_slot[NNZ];
__device__ int   g_u_ptr[N_USERS + 1];
__device__ int   g_i_ptr[N_ITEMS + 1];
__device__ int   g_i_cnt[N_ITEMS];
__device__ int   g_part[SCAN_BLOCKS];
__device__ int   g_partpre[SCAN_BLOCKS];

// ---------------- helpers ----------------
__device__ __forceinline__ void acc8(float2& a0, float2& a1, float2& a2, float2& a3,
                                     uint4 v, float w) {
    float2 b;
    b = __half22float2(*(__half2*)&v.x); a0.x = fmaf(w, b.x, a0.x); a0.y = fmaf(w, b.y, a0.y);
    b = __half22float2(*(__half2*)&v.y); a1.x = fmaf(w, b.x, a1.x); a1.y = fmaf(w, b.y, a1.y);
    b = __half22float2(*(__half2*)&v.z); a2.x = fmaf(w, b.x, a2.x); a2.y = fmaf(w, b.y, a2.y);
    b = __half22float2(*(__half2*)&v.w); a3.x = fmaf(w, b.x, a3.x); a3.y = fmaf(w, b.y, a3.y);
}
__device__ __forceinline__ uint4 pack8(float2 a0, float2 a1, float2 a2, float2 a3) {
    uint4 r;
    *(__half2*)&r.x = __floats2half2_rn(a0.x, a0.y);
    *(__half2*)&r.y = __floats2half2_rn(a1.x, a1.y);
    *(__half2*)&r.z = __floats2half2_rn(a2.x, a2.y);
    *(__half2*)&r.w = __floats2half2_rn(a3.x, a3.y);
    return r;
}
__device__ __forceinline__ void xor_reduce_groups(float2& a0, float2& a1, float2& a2, float2& a3) {
    #pragma unroll
    for (int o = 8; o <= 16; o <<= 1) {
        a0.x += __shfl_xor_sync(0xffffffffu, a0.x, o);
        a0.y += __shfl_xor_sync(0xffffffffu, a0.y, o);
        a1.x += __shfl_xor_sync(0xffffffffu, a1.x, o);
        a1.y += __shfl_xor_sync(0xffffffffu, a1.y, o);
        a2.x += __shfl_xor_sync(0xffffffffu, a2.x, o);
        a2.y += __shfl_xor_sync(0xffffffffu, a2.y, o);
        a3.x += __shfl_xor_sync(0xffffffffu, a3.x, o);
        a3.y += __shfl_xor_sync(0xffffffffu, a3.y, o);
    }
}

// ---------------- CSR construction ----------------
__global__ void k_uptr(const int* __restrict__ u_idx) {
    int t = blockIdx.x * blockDim.x + threadIdx.x;
    if (t < N_ITEMS) g_i_cnt[t] = 0;
    if (t > N_USERS) return;
    int lo = 0, hi = NNZ;
    while (lo < hi) { int mid = (lo + hi) >> 1; if (u_idx[mid] < t) lo = mid + 1; else hi = mid; }
    g_u_ptr[t] = lo;
}

__global__ void k_count(const int* __restrict__ i_idx) {
    int e = blockIdx.x * blockDim.x + threadIdx.x;
    if (e < NNZ) atomicAdd(&g_i_cnt[i_idx[e]], 1);
}

__global__ void __launch_bounds__(256) k_part() {
    __shared__ int wsum[8];
    int b = blockIdx.x, tid = threadIdx.x;
    int s = 0;
    for (int k = tid; k < SCAN_CHUNK; k += 256) s += g_i_cnt[b * SCAN_CHUNK + k];
    #pragma unroll
    for (int o = 16; o; o >>= 1) s += __shfl_xor_sync(0xffffffffu, s, o);
    if ((tid & 31) == 0) wsum[tid >> 5] = s;
    __syncthreads();
    if (tid < 8) {
        int x = wsum[tid];
        #pragma unroll
        for (int o = 4; o; o >>= 1) x += __shfl_xor_sync(0xffu, x, o);
        if (tid == 0) g_part[b] = x;
    }
}

__global__ void k_scanpart() {
    int t = threadIdx.x;
    int x = (t < SCAN_BLOCKS) ? g_part[t] : 0;
    int incl = x;
    #pragma unroll
    for (int o = 1; o < 32; o <<= 1) { int y = __shfl_up_sync(0xffffffffu, incl, o); if (t >= o) incl += y; }
    if (t < SCAN_BLOCKS) g_partpre[t] = incl - x;
}

__global__ void __launch_bounds__(1024) k_blkscan() {
    __shared__ int wsum[32];
    int b = blockIdx.x, tid = threadIdx.x, lane = tid & 31, wid = tid >> 5;
    int idx = b * SCAN_CHUNK + tid;
    int x = (tid < SCAN_CHUNK) ? g_i_cnt[idx] : 0;
    int t = x;
    #pragma unroll
    for (int o = 1; o < 32; o <<= 1) { int y = __shfl_up_sync(0xffffffffu, t, o); if (lane >= o) t += y; }
    if (lane == 31) wsum[wid] = t;
    __syncthreads();
    if (wid == 0) {
        int s = wsum[lane];
        #pragma unroll
        for (int o = 1; o < 32; o <<= 1) { int y = __shfl_up_sync(0xffffffffu, s, o); if (lane >= o) s += y; }
        wsum[lane] = s;
    }
    __syncthreads();
    int incl = t + (wid ? wsum[wid - 1] : 0);
    if (tid < SCAN_CHUNK) {
        g_i_ptr[idx] = g_partpre[b] + incl - x;   // exclusive prefix
        g_i_cnt[idx] = 0;
    }
    if (b == SCAN_BLOCKS - 1 && tid == 0) g_i_ptr[N_ITEMS] = NNZ;
}

__global__ void k_scatter(const int* __restrict__ u_idx, const int* __restrict__ i_idx) {
    int e = blockIdx.x * blockDim.x + threadIdx.x;
    if (e >= NNZ) return;
    int i = i_idx[e];
    int pos = g_i_ptr[i] + atomicAdd(&g_i_cnt[i], 1);
    g_i_src_u[pos] = u_idx[e];
    g_slot[e] = pos;
}

// ---------------- fp16 conversion ----------------
__global__ void k_cvt(const float* __restrict__ user_linear, const float* __restrict__ item_linear) {
    int j = blockIdx.x * blockDim.x + threadIdx.x;
    const int NU = N_ITEMS * 8;
    const int NI = N_USERS * 8;
    if (j < NU) {
        const float4* s = (const float4*)user_linear;
        float4 x0 = s[2 * j], x1 = s[2 * j + 1];
        g_lin_u[j] = pack8(make_float2(x0.x, x0.y), make_float2(x0.z, x0.w),
                           make_float2(x1.x, x1.y), make_float2(x1.z, x1.w));
    } else if (j < NU + NI) {
        int k = j - NU;
        const float4* s = (const float4*)item_linear;
        float4 x0 = s[2 * k], x1 = s[2 * k + 1];
        g_lin_i[k] = pack8(make_float2(x0.x, x0.y), make_float2(x0.z, x0.w),
                           make_float2(x1.x, x1.y), make_float2(x1.z, x1.w));
    }
}

// ---------------- base embeddings (warp per row, 8 lanes per gathered row) ----------------
__global__ void __launch_bounds__(256) k_emb(const int* __restrict__ i_idx,
                                             float* __restrict__ out) {
    int r = (blockIdx.x * blockDim.x + threadIdx.x) >> 5;
    if (r >= N_TOTAL) return;
    int lane = threadIdx.x & 31, g = lane >> 3, c = lane & 7;
    const uint4* src;
    const int* idxarr;
    int beg, end, row;
    if (r < N_USERS) {
        row = r; src = g_lin_u; idxarr = i_idx;
        beg = g_u_ptr[r]; end = g_u_ptr[r + 1];
    } else {
        row = r - N_USERS; src = g_lin_i; idxarr = g_i_src_u;
        beg = g_i_ptr[row]; end = g_i_ptr[row + 1];
    }
    float2 a0 = {0,0}, a1 = {0,0}, a2 = {0,0}, a3 = {0,0};
    for (int ch = beg; ch < end; ch += 4) {
        int e = ch + g;
        bool val = e < end;
        int idx = val ? idxarr[e] : 0;
        uint4 v = src[idx * 8 + c];
        acc8(a0, a1, a2, a3, v, val ? 1.0f : 0.0f);
    }
    xor_reduce_groups(a0, a1, a2, a3);
    // row norm: sum of squares over this lane's 8 cols, reduce within group
    float ss = a0.x*a0.x + a0.y*a0.y + a1.x*a1.x + a1.y*a1.y
             + a2.x*a2.x + a2.y*a2.y + a3.x*a3.x + a3.y*a3.y;
    #pragma unroll
    for (int o = 1; o <= 4; o <<= 1) ss += __shfl_xor_sync(0xffffffffu, ss, o);
    if (lane == 0) {
        float inv = 1.0f / fmaxf(sqrtf(ss), EPS);
        if (r < N_USERS) g_inv_u[row] = inv; else g_inv_i[row] = inv;
    }
    if (g == 0) {
        if (r < N_USERS) g_emb_u0[row * 8 + c] = pack8(a0, a1, a2, a3);
        else             g_emb_i0[row * 8 + c] = pack8(a0, a1, a2, a3);
        float4* o = (float4*)(out + (size_t)r * D + c * 8);
        o[0] = make_float4(a0.x, a0.y, a1.x, a1.y);
        o[1] = make_float4(a2.x, a2.y, a3.x, a3.y);
    }
}

// ---------------- weights + u-side norm + u-side packing (warp per user) ----------------
__global__ void __launch_bounds__(256) k_weights(const int* __restrict__ i_idx) {
    int u = (blockIdx.x * blockDim.x + threadIdx.x) >> 5;
    if (u >= N_USERS) return;
    int lane = threadIdx.x & 31, g = lane >> 3, c = lane & 7;
    int beg = g_u_ptr[u], end = g_u_ptr[u + 1];
    uint4 av = g_emb_u0[u * 8 + c];
    float2 A0 = __half22float2(*(__half2*)&av.x);
    float2 A1 = __half22float2(*(__half2*)&av.y);
    float2 A2 = __half22float2(*(__half2*)&av.z);
    float2 A3 = __half22float2(*(__half2*)&av.w);
    float invu = g_inv_u[u];
    float sum = 0.f;
    for (int ch = beg; ch < end; ch += 4) {
        int e = ch + g;
        bool val = e < end;
        int i = val ? i_idx[e] : 0;
        uint4 bv = g_emb_i0[i * 8 + c];
        float2 b;
        float d = 0.f;
        b = __half22float2(*(__half2*)&bv.x); d = fmaf(A0.x, b.x, d); d = fmaf(A0.y, b.y, d);
        b = __half22float2(*(__half2*)&bv.y); d = fmaf(A1.x, b.x, d); d = fmaf(A1.y, b.y, d);
        b = __half22float2(*(__half2*)&bv.z); d = fmaf(A2.x, b.x, d); d = fmaf(A2.y, b.y, d);
        b = __half22float2(*(__half2*)&bv.w); d = fmaf(A3.x, b.x, d); d = fmaf(A3.y, b.y, d);
        #pragma unroll
        for (int o = 1; o <= 4; o <<= 1) d += __shfl_xor_sync(0xffffffffu, d, o);
        if (c == 0 && val) {
            float s = d * invu * g_inv_i[i];
            float w = fmaf(s, 0.5f, 0.5f);
            g_w_u[e] = w;
            g_w_i[g_slot[e]] = w;
            sum += w;
        }
    }
    sum += __shfl_xor_sync(0xffffffffu, sum, 8);
    sum += __shfl_xor_sync(0xffffffffu, sum, 16);
    float invd = 1.0f / (sum + 1e-7f);
    invd = __shfl_sync(0xffffffffu, invd, 0);
    __syncwarp();
    __threadfence_block();
    for (int e = beg + lane; e < end; e += 32)
        g_pk_u[e] = make_int2(i_idx[e], __float_as_int(g_w_u[e] * invd));
}

// ---------------- i-side norm + packing (warp per item) ----------------
__global__ void __launch_bounds__(256) k_norm_i() {
    int i = (blockIdx.x * blockDim.x + threadIdx.x) >> 5;
    if (i >= N_ITEMS) return;
    int lane = threadIdx.x & 31;
    int beg = g_i_ptr[i], end = g_i_ptr[i + 1];
    float s = 0.f;
    for (int p = beg + lane; p < end; p += 32) s += g_w_i[p];
    #pragma unroll
    for (int o = 16; o; o >>= 1) s += __shfl_xor_sync(0xffffffffu, s, o);
    float invd = 1.0f / (s + 1e-7f);
    for (int p = beg + lane; p < end; p += 32)
        g_pk_i[p] = make_int2(g_i_src_u[p], __float_as_int(g_w_i[p] * invd));
}

// ---------------- fused propagation layer ----------------
__global__ void __launch_bounds__(256) k_prop(float* __restrict__ out, int flip, float scale) {
    int r = (blockIdx.x * blockDim.x + threadIdx.x) >> 5;
    if (r >= N_TOTAL) return;
    int lane = threadIdx.x & 31, g = lane >> 3, c = lane & 7;
    const int2* pk;
    const uint4* src;
    uint4* dst;
    int beg, end, row;
    if (r < N_USERS) {
        row = r; pk = g_pk_u;
        src = flip ? g_emb_i1 : g_emb_i0;
        dst = flip ? g_emb_u0 : g_emb_u1;
        beg = g_u_ptr[r]; end = g_u_ptr[r + 1];
    } else {
        row = r - N_USERS; pk = g_pk_i;
        src = flip ? g_emb_u1 : g_emb_u0;
        dst = flip ? g_emb_i0 : g_emb_i1;
        beg = g_i_ptr[row]; end = g_i_ptr[row + 1];
    }
    float2 a0 = {0,0}, a1 = {0,0}, a2 = {0,0}, a3 = {0,0};
    for (int ch = beg; ch < end; ch += 4) {
        int e = ch + g;
        int2 p = (e < end) ? pk[e] : make_int2(0, 0);
        float w = __int_as_float(p.y);
        uint4 v = src[p.x * 8 + c];
        acc8(a0, a1, a2, a3, v, w);
    }
    xor_reduce_groups(a0, a1, a2, a3);
    if (g == 0) {
        dst[row * 8 + c] = pack8(a0, a1, a2, a3);
        float4* o = (float4*)(out + (size_t)r * D + c * 8);
        float4 o0 = o[0], o1 = o[1];
        o0.x = (o0.x + a0.x) * scale; o0.y = (o0.y + a0.y) * scale;
        o0.z = (o0.z + a1.x) * scale; o0.w = (o0.w + a1.y) * scale;
        o1.x = (o1.x + a2.x) * scale; o1.y = (o1.y + a2.y) * scale;
        o1.z = (o1.z + a3.x) * scale; o1.w = (o1.w + a3.y) * scale;
        o[0] = o0; o[1] = o1;
    }
}

// ---------------- launch ----------------
extern "C" void kernel_launch(void* const* d_in, const int* in_sizes, int n_in,
                              void* d_out, int out_size) {
    const float* user_linear = (const float*)d_in[0];
    const float* item_linear = (const float*)d_in[1];
    const int*   u_idx       = (const int*)d_in[2];
    const int*   i_idx       = (const int*)d_in[3];
    float* out = (float*)d_out;

    k_uptr<<<(N_USERS + 1 + 255) / 256, 256>>>(u_idx);
    k_count<<<(NNZ + 255) / 256, 256>>>(i_idx);
    k_part<<<SCAN_BLOCKS, 256>>>();
    k_scanpart<<<1, 32>>>();
    k_blkscan<<<SCAN_BLOCKS, 1024>>>();
    k_scatter<<<(NNZ + 255) / 256, 256>>>(u_idx, i_idx);
    {
        int total = (N_ITEMS + N_USERS) * 8;
        k_cvt<<<(total + 255) / 256, 256>>>(user_linear, item_linear);
    }

    k_emb<<<(N_TOTAL * 32 + 255) / 256, 256>>>(i_idx, out);
    k_weights<<<(N_USERS * 32 + 255) / 256, 256>>>(i_idx);
    k_norm_i<<<(N_ITEMS * 32 + 255) / 256, 256>>>();

    k_prop<<<(N_TOTAL * 32 + 255) / 256, 256>>>(out, 0, 1.0f);
    k_prop<<<(N_TOTAL * 32 + 255) / 256, 256>>>(out, 1, 1.0f);
    k_prop<<<(N_TOTAL * 32 + 255) / 256, 256>>>(out, 0, 0.25f);
}